// round 4
// baseline (speedup 1.0000x reference)
#include <cuda_runtime.h>
#include <cuda_bf16.h>
#include <cstdint>
#include <math.h>

#define BB 32
#define TT 2048
#define DD 512
#define UU 512

#define TCH 32
#define TCHUNK (TT / TCH)   // 64

// ---- scratch ----
__device__ float g_hb[BB * UU];
__device__ float g_scores[BB * TT];
__device__ float g_m[BB];
__device__ float g_z[BB];
__device__ float g_part[BB * TCH * DD];
__device__ __nv_bfloat16 g_wt_hi[UU * DD];      // W1^T hi [u][d]
__device__ __nv_bfloat16 g_wt_lo[UU * DD];      // W1^T lo [u][d]

// ---------------- helpers ----------------
static __device__ __forceinline__ unsigned pack2(__nv_bfloat16 a, __nv_bfloat16 b) {
    return (unsigned)__bfloat16_as_ushort(a) |
           ((unsigned)__bfloat16_as_ushort(b) << 16);
}
static __device__ __forceinline__ float fast_tanh(float x) {
    float e = __expf(2.f * x);
    return 1.f - __fdividef(2.f, e + 1.f);
}
static __device__ __forceinline__ void mma16816(float* c, const unsigned* a, const unsigned* b) {
    asm volatile(
        "mma.sync.aligned.m16n8k16.row.col.f32.bf16.bf16.f32 "
        "{%0,%1,%2,%3}, {%4,%5,%6,%7}, {%8,%9}, {%0,%1,%2,%3};"
        : "+f"(c[0]), "+f"(c[1]), "+f"(c[2]), "+f"(c[3])
        : "r"(a[0]), "r"(a[1]), "r"(a[2]), "r"(a[3]), "r"(b[0]), "r"(b[1]));
}
static __device__ __forceinline__ void ldm4(unsigned* r, const void* p) {
    unsigned addr = (unsigned)__cvta_generic_to_shared(p);
    asm volatile(
        "ldmatrix.sync.aligned.m8n8.x4.shared.b16 {%0,%1,%2,%3}, [%4];"
        : "=r"(r[0]), "=r"(r[1]), "=r"(r[2]), "=r"(r[3])
        : "r"(addr));
}
static __device__ __forceinline__ void cp16(void* dst, const void* src) {
    unsigned d = (unsigned)__cvta_generic_to_shared(dst);
    asm volatile("cp.async.cg.shared.global [%0], [%1], 16;"
                 :: "r"(d), "l"(src) : "memory");
}
static __device__ __forceinline__ void cp_commit() {
    asm volatile("cp.async.commit_group;" ::: "memory");
}
static __device__ __forceinline__ void cp_wait1() {
    asm volatile("cp.async.wait_group 1;" ::: "memory");
}
static __device__ __forceinline__ void cp_wait0() {
    asm volatile("cp.async.wait_group 0;" ::: "memory");
}

// smem layout (bytes)
#define PADA 520                          // A row stride in halves
#define PADB 40                           // B row stride in halves
#define OFF_HB   0
#define OFF_VS   512
#define OFF_RED  1024
#define OFF_B    2048                     // 2 stages x (hi 10240 + lo 10240)
#define B_STAGE_H 10240                   // halves per stage (hi+lo)
#define B_HALF_H  5120                    // halves in one hi (or lo) plane
#define OFF_AHI  (2048 + 40960)           // 43008
#define OFF_ALO  (OFF_AHI + 64 * PADA * 2)
#define SMEM_TOTAL (OFF_ALO + 64 * PADA * 2)   // 176128

// ---------------------------------------------------------------------------
// Kernel 0: split + transpose W1
// ---------------------------------------------------------------------------
__global__ void k_prep(const float* __restrict__ W1) {
    int d = blockIdx.x;
    int u = threadIdx.x;
    float x = W1[d * UU + u];
    __nv_bfloat16 hi = __float2bfloat16_rn(x);
    __nv_bfloat16 lo = __float2bfloat16_rn(x - __bfloat162float(hi));
    g_wt_hi[u * DD + d] = hi;
    g_wt_lo[u * DD + d] = lo;
}

// ---------------------------------------------------------------------------
// Kernel 1: g_hb[b,u] = last[b,:] @ W2[:,u] + b1[u] + b2[u]
// ---------------------------------------------------------------------------
__global__ void k_h2(const float* __restrict__ last, const float* __restrict__ W2,
                     const float* __restrict__ b1, const float* __restrict__ b2) {
    int b = blockIdx.x;
    int u = threadIdx.x;
    __shared__ float sl[DD];
    sl[u] = last[b * DD + u];
    __syncthreads();
    float acc = 0.f;
#pragma unroll 8
    for (int d = 0; d < DD; ++d)
        acc += sl[d] * W2[d * UU + u];
    g_hb[b * UU + u] = acc + b1[u] + b2[u];
}

// ---------------------------------------------------------------------------
// Kernel 2: scores. CTA = 64t x 512u(4 passes) x 512k. A resident bf16 hi/lo
// in smem (converted once); B (W1^T hi/lo) streamed via cp.async double buffer.
// Split-bf16 3-term mma.sync; fused tanh/V epilogue -> complete scores.
// ---------------------------------------------------------------------------
__global__ __launch_bounds__(256, 1) void k_score(
    const float* __restrict__ full,
    const float* __restrict__ V, const float* __restrict__ bV) {
    extern __shared__ __align__(16) char smem[];
    float* hb_s = (float*)(smem + OFF_HB);
    float* vs_s = (float*)(smem + OFF_VS);
    float* red  = (float*)(smem + OFF_RED);
    __nv_bfloat16* sB   = (__nv_bfloat16*)(smem + OFF_B);
    __nv_bfloat16* sAhi = (__nv_bfloat16*)(smem + OFF_AHI);
    __nv_bfloat16* sAlo = (__nv_bfloat16*)(smem + OFF_ALO);

    const int tid = threadIdx.x;
    const int wid = tid >> 5;
    const int lane = tid & 31;
    const int g = lane >> 2;
    const int t = lane & 3;
    const int mw = wid >> 2;        // 0..1 (t dimension)
    const int nw = wid & 3;         // 0..3 (u dimension)
    const int mbase = mw * 32;
    const int nbase = nw * 32;

    const int b  = blockIdx.y;
    const int t0 = blockIdx.x * 64;

    // ldmatrix per-lane offsets (halves)
    const int tile = lane >> 3;
    const int rr = lane & 7;
    const int a_lane_off = ((tile & 1) * 8 + rr) * PADA + ((tile >> 1) & 1) * 8;
    const int b_lane_off = (((tile >> 1) & 1) * 8 + rr) * PADB + (tile & 1) * 8;

    // ---- convert A tile (64 x 512 fp32 -> bf16 hi/lo), resident ----
    {
        const float* Ab = full + ((size_t)(b * TT + t0)) * DD;
#pragma unroll
        for (int it = 0; it < 32; ++it) {
            int idx = tid + it * 256;      // 0..8191 float4s
            int r = idx >> 7;              // row 0..63
            int q = idx & 127;             // float4 within row
            float4 v4 = *(const float4*)(Ab + (size_t)r * DD + q * 4);
            __nv_bfloat16 h0 = __float2bfloat16_rn(v4.x);
            __nv_bfloat16 h1 = __float2bfloat16_rn(v4.y);
            __nv_bfloat16 h2 = __float2bfloat16_rn(v4.z);
            __nv_bfloat16 h3 = __float2bfloat16_rn(v4.w);
            uint2 hv, lv;
            hv.x = pack2(h0, h1); hv.y = pack2(h2, h3);
            lv.x = pack2(__float2bfloat16_rn(v4.x - __bfloat162float(h0)),
                         __float2bfloat16_rn(v4.y - __bfloat162float(h1)));
            lv.y = pack2(__float2bfloat16_rn(v4.z - __bfloat162float(h2)),
                         __float2bfloat16_rn(v4.w - __bfloat162float(h3)));
            *(uint2*)(sAhi + r * PADA + q * 4) = hv;
            *(uint2*)(sAlo + r * PADA + q * 4) = lv;
        }
    }

    // ---- B prefetch lambda: chunk (uc,c) -> stage ----
    auto issueB = [&](int uc_, int c_, int stage) {
        const int u0 = uc_ * 128;
        const int k0 = c_ * 32;
#pragma unroll
        for (int j = 0; j < 4; ++j) {
            int op  = tid + j * 256;        // 0..1023
            int arr = op >> 9;              // 0 hi, 1 lo
            int o   = op & 511;
            int row = o >> 2;
            int q   = o & 3;
            const __nv_bfloat16* src =
                (arr ? g_wt_lo : g_wt_hi) + (size_t)(u0 + row) * DD + k0 + q * 8;
            __nv_bfloat16* dst =
                sB + stage * B_STAGE_H + arr * B_HALF_H + row * PADB + q * 8;
            cp16(dst, src);
        }
        cp_commit();
    };

    float s[4];
#pragma unroll
    for (int i = 0; i < 4; ++i) s[i] = 0.f;

    issueB(0, 0, 0);

    for (int uc = 0; uc < 4; ++uc) {
        __syncthreads();                    // previous epilogue done reading hb/vs
        if (tid < 128) {
            hb_s[tid] = g_hb[b * UU + uc * 128 + tid];
            vs_s[tid] = V[uc * 128 + tid];
        }

        float acc[32];
#pragma unroll
        for (int i = 0; i < 32; ++i) acc[i] = 0.f;

        for (int c = 0; c < 16; ++c) {
            const int gc = uc * 16 + c;
            const int stage = gc & 1;
            if (gc < 63) {
                int nuc = (c == 15) ? uc + 1 : uc;
                int nc  = (c == 15) ? 0 : c + 1;
                issueB(nuc, nc, (gc + 1) & 1);
                cp_wait1();
            } else {
                cp_wait0();
            }
            __syncthreads();

            const __nv_bfloat16* Bh = sB + stage * B_STAGE_H;
            const __nv_bfloat16* Bl = Bh + B_HALF_H;
            const int k0 = c * 32;
#pragma unroll
            for (int kk = 0; kk < 32; kk += 16) {
                unsigned bh[8], bl[8];
#pragma unroll
                for (int p = 0; p < 2; ++p) {
                    ldm4(bh + 4 * p, Bh + (nbase + p * 16) * PADB + kk + b_lane_off);
                    ldm4(bl + 4 * p, Bl + (nbase + p * 16) * PADB + kk + b_lane_off);
                }
#pragma unroll
                for (int mt = 0; mt < 2; ++mt) {
                    unsigned ah[4], al[4];
                    ldm4(ah, sAhi + (mbase + mt * 16) * PADA + k0 + kk + a_lane_off);
                    ldm4(al, sAlo + (mbase + mt * 16) * PADA + k0 + kk + a_lane_off);
#pragma unroll
                    for (int nt = 0; nt < 4; ++nt) {
                        float* cc = acc + (mt * 4 + nt) * 4;
                        mma16816(cc, ah, bh + 2 * nt);
                        mma16816(cc, ah, bl + 2 * nt);
                        mma16816(cc, al, bh + 2 * nt);
                    }
                }
            }
            __syncthreads();                // all warps done before buffer reuse
        }

        // ---- epilogue for this u-chunk: tanh + dot with V ----
#pragma unroll
        for (int mt = 0; mt < 2; ++mt) {
#pragma unroll
            for (int nt = 0; nt < 4; ++nt) {
                const float* cc = acc + (mt * 4 + nt) * 4;
                int n0 = nbase + nt * 8 + 2 * t;
                s[mt * 2 + 0] += fast_tanh(cc[0] + hb_s[n0]) * vs_s[n0]
                               + fast_tanh(cc[1] + hb_s[n0 + 1]) * vs_s[n0 + 1];
                s[mt * 2 + 1] += fast_tanh(cc[2] + hb_s[n0]) * vs_s[n0]
                               + fast_tanh(cc[3] + hb_s[n0 + 1]) * vs_s[n0 + 1];
            }
        }
    }

    // ---- reduce over t lanes (width 4), then over 4 nw warps via smem ----
#pragma unroll
    for (int i = 0; i < 4; ++i) {
        float v = s[i];
        v += __shfl_xor_sync(0xffffffffu, v, 1, 4);
        v += __shfl_xor_sync(0xffffffffu, v, 2, 4);
        if (t == 0) {
            int mt = i >> 1, half = i & 1;
            int row = mbase + mt * 16 + half * 8 + g;
            red[nw * 64 + row] = v;
        }
    }
    __syncthreads();
    if (tid < 64) {
        float sum = red[tid] + red[64 + tid] + red[128 + tid] + red[192 + tid];
        g_scores[b * TT + t0 + tid] = sum + bV[0];
    }
}

// ---------------------------------------------------------------------------
// Kernel 3: softmax stats (single pass, scores in registers)
// ---------------------------------------------------------------------------
__global__ void k_stats() {
    int b = blockIdx.x;
    int tid = threadIdx.x;   // 256
    __shared__ float red[256];

    float v[8];
    const float4* sp = (const float4*)(g_scores + b * TT) + tid * 2;
    float4 a0 = sp[0], a1 = sp[1];
    v[0] = a0.x; v[1] = a0.y; v[2] = a0.z; v[3] = a0.w;
    v[4] = a1.x; v[5] = a1.y; v[6] = a1.z; v[7] = a1.w;

    float m = -INFINITY;
#pragma unroll
    for (int i = 0; i < 8; ++i) m = fmaxf(m, v[i]);
    red[tid] = m;
    __syncthreads();
    for (int sft = 128; sft > 0; sft >>= 1) {
        if (tid < sft) red[tid] = fmaxf(red[tid], red[tid + sft]);
        __syncthreads();
    }
    m = red[0];
    __syncthreads();

    float z = 0.f;
#pragma unroll
    for (int i = 0; i < 8; ++i) z += expf(v[i] - m);
    red[tid] = z;
    __syncthreads();
    for (int sft = 128; sft > 0; sft >>= 1) {
        if (tid < sft) red[tid] += red[tid + sft];
        __syncthreads();
    }
    if (tid == 0) { g_m[b] = m; g_z[b] = red[0]; }
}

// ---------------------------------------------------------------------------
// Kernel 4: partial weighted sums
// ---------------------------------------------------------------------------
__global__ __launch_bounds__(128) void k_context(const float* __restrict__ full) {
    int b  = blockIdx.y;
    int tc = blockIdx.x;
    int tid = threadIdx.x;
    __shared__ float ws[TCHUNK];

    float m = g_m[b];
    if (tid < TCHUNK)
        ws[tid] = expf(g_scores[b * TT + tc * TCHUNK + tid] - m);
    __syncthreads();

    const float4* fp =
        (const float4*)(full + ((size_t)(b * TT + tc * TCHUNK)) * DD) + tid;
    float4 acc = make_float4(0.f, 0.f, 0.f, 0.f);
#pragma unroll 8
    for (int t = 0; t < TCHUNK; ++t) {
        float4 f = fp[(size_t)t * (DD / 4)];
        float w = ws[t];
        acc.x += w * f.x;
        acc.y += w * f.y;
        acc.z += w * f.z;
        acc.w += w * f.w;
    }
    float4* pp = (float4*)(g_part + ((size_t)(b * TCH + tc)) * DD) + tid;
    *pp = acc;
}

// ---------------------------------------------------------------------------
// Kernel 5: combine partials
// ---------------------------------------------------------------------------
__global__ void k_combine(float* __restrict__ out) {
    int idx = blockIdx.x * 256 + threadIdx.x;
    if (idx >= BB * DD) return;
    int b = idx / DD;
    int d = idx - b * DD;
    float acc = 0.f;
#pragma unroll
    for (int tc = 0; tc < TCH; ++tc)
        acc += g_part[((size_t)(b * TCH + tc)) * DD + d];
    out[idx] = acc / g_z[b];
}

// ---------------------------------------------------------------------------
extern "C" void kernel_launch(void* const* d_in, const int* in_sizes, int n_in,
                              void* d_out, int out_size) {
    const float* full = (const float*)d_in[0];
    const float* last = (const float*)d_in[1];
    const float* W1   = (const float*)d_in[2];
    const float* b1   = (const float*)d_in[3];
    const float* W2   = (const float*)d_in[4];
    const float* b2   = (const float*)d_in[5];
    const float* V    = (const float*)d_in[6];
    const float* bV   = (const float*)d_in[7];
    float* out = (float*)d_out;

    cudaFuncSetAttribute(k_score, cudaFuncAttributeMaxDynamicSharedMemorySize,
                         SMEM_TOTAL);

    k_prep<<<DD, UU>>>(W1);
    k_h2<<<BB, DD>>>(last, W2, b1, b2);

    dim3 gScore(TT / 64, BB);
    k_score<<<gScore, 256, SMEM_TOTAL>>>(full, V, bV);

    k_stats<<<BB, 256>>>();

    dim3 gCtx(TCH, BB);
    k_context<<<gCtx, 128>>>(full);

    k_combine<<<(BB * DD + 255) / 256, 256>>>(out);
}

// round 5
// speedup vs baseline: 1.3870x; 1.3870x over previous
#include <cuda_runtime.h>
#include <cuda_fp16.h>
#include <cstdint>
#include <math.h>

#define BB 32
#define TT 2048
#define DD 512
#define UU 512

#define TCH 32
#define TCHUNK (TT / TCH)   // 64

// ---- scratch ----
__device__ float g_hb[BB * UU];
__device__ float g_scores[BB * TT];
__device__ float g_m[BB];
__device__ float g_z[BB];
__device__ float g_part[BB * TCH * DD];
__device__ __half g_wt_hi[UU * DD];      // W1^T hi [u][d] fp16
__device__ __half g_wt_lo[UU * DD];      // W1^T lo [u][d] fp16

// ---------------- helpers ----------------
static __device__ __forceinline__ unsigned pack2h(__half a, __half b) {
    return (unsigned)__half_as_ushort(a) |
           ((unsigned)__half_as_ushort(b) << 16);
}
static __device__ __forceinline__ float fast_tanh(float x) {
    float e = __expf(2.f * x);
    return 1.f - __fdividef(2.f, e + 1.f);
}
static __device__ __forceinline__ void mma16816(float* c, const unsigned* a, const unsigned* b) {
    asm volatile(
        "mma.sync.aligned.m16n8k16.row.col.f32.f16.f16.f32 "
        "{%0,%1,%2,%3}, {%4,%5,%6,%7}, {%8,%9}, {%0,%1,%2,%3};"
        : "+f"(c[0]), "+f"(c[1]), "+f"(c[2]), "+f"(c[3])
        : "r"(a[0]), "r"(a[1]), "r"(a[2]), "r"(a[3]), "r"(b[0]), "r"(b[1]));
}
static __device__ __forceinline__ void ldm4(unsigned* r, const void* p) {
    unsigned addr = (unsigned)__cvta_generic_to_shared(p);
    asm volatile(
        "ldmatrix.sync.aligned.m8n8.x4.shared.b16 {%0,%1,%2,%3}, [%4];"
        : "=r"(r[0]), "=r"(r[1]), "=r"(r[2]), "=r"(r[3])
        : "r"(addr));
}
static __device__ __forceinline__ void cp16(void* dst, const void* src) {
    unsigned d = (unsigned)__cvta_generic_to_shared(dst);
    asm volatile("cp.async.cg.shared.global [%0], [%1], 16;"
                 :: "r"(d), "l"(src) : "memory");
}
static __device__ __forceinline__ void cp_commit() {
    asm volatile("cp.async.commit_group;" ::: "memory");
}
static __device__ __forceinline__ void cp_wait1() {
    asm volatile("cp.async.wait_group 1;" ::: "memory");
}
static __device__ __forceinline__ void cp_wait0() {
    asm volatile("cp.async.wait_group 0;" ::: "memory");
}

// smem layout
#define PADA 520                            // A row stride (halves)
#define PADB 40                             // B row stride (halves)
#define OFF_HB   0
#define OFF_VS   512
#define OFF_RED  1024
#define OFF_B    2048
#define B_STAGE_H (2 * 128 * PADB)          // hi+lo planes per stage (halves) = 10240
#define B_HALF_H  (128 * PADB)              // one plane (halves) = 5120
#define OFF_A    (OFF_B + 2 * B_STAGE_H * 2)   // 2048 + 40960 = 43008
#define SMEM_TOTAL (OFF_A + 64 * PADA * 2)     // 43008 + 66560 = 109568

// ---------------------------------------------------------------------------
// Kernel 0: split + transpose W1 -> fp16 hi/lo [u][d]
// ---------------------------------------------------------------------------
__global__ void k_prep(const float* __restrict__ W1) {
    int d = blockIdx.x;
    int u = threadIdx.x;
    float x = W1[d * UU + u];
    __half hi = __float2half_rn(x);
    __half lo = __float2half_rn(x - __half2float(hi));
    g_wt_hi[u * DD + d] = hi;
    g_wt_lo[u * DD + d] = lo;
}

// ---------------------------------------------------------------------------
// Kernel 1: g_hb[b,u] = last[b,:] @ W2[:,u] + b1[u] + b2[u]   (fp32)
// ---------------------------------------------------------------------------
__global__ void k_h2(const float* __restrict__ last, const float* __restrict__ W2,
                     const float* __restrict__ b1, const float* __restrict__ b2) {
    int b = blockIdx.x;
    int u = threadIdx.x;
    __shared__ float sl[DD];
    sl[u] = last[b * DD + u];
    __syncthreads();
    float acc = 0.f;
#pragma unroll 8
    for (int d = 0; d < DD; ++d)
        acc += sl[d] * W2[d * UU + u];
    g_hb[b * UU + u] = acc + b1[u] + b2[u];
}

// ---------------------------------------------------------------------------
// Kernel 2: scores. CTA = 64t x 512u(4 passes) x 512k.
// A: fp16 (single rounding), converted once, resident in smem.
// B: W1^T hi/lo fp16 streamed via cp.async double buffer.
// 2-term mma.sync: a*w_hi + a*w_lo. Fused tanh/V epilogue.
// ---------------------------------------------------------------------------
__global__ __launch_bounds__(256, 2) void k_score(
    const float* __restrict__ full,
    const float* __restrict__ V, const float* __restrict__ bV) {
    extern __shared__ __align__(16) char smem[];
    float* hb_s = (float*)(smem + OFF_HB);
    float* vs_s = (float*)(smem + OFF_VS);
    float* red  = (float*)(smem + OFF_RED);
    __half* sB  = (__half*)(smem + OFF_B);
    __half* sA  = (__half*)(smem + OFF_A);

    const int tid = threadIdx.x;
    const int wid = tid >> 5;
    const int lane = tid & 31;
    const int g = lane >> 2;
    const int t = lane & 3;
    const int mw = wid >> 2;        // 0..1
    const int nw = wid & 3;         // 0..3
    const int mbase = mw * 32;
    const int nbase = nw * 32;

    const int b  = blockIdx.y;
    const int t0 = blockIdx.x * 64;

    const int tile = lane >> 3;
    const int rr = lane & 7;
    const int a_lane_off = ((tile & 1) * 8 + rr) * PADA + ((tile >> 1) & 1) * 8;
    const int b_lane_off = (((tile >> 1) & 1) * 8 + rr) * PADB + (tile & 1) * 8;

    // ---- convert A tile (64 x 512 fp32 -> fp16), resident ----
    {
        const float* Ab = full + ((size_t)(b * TT + t0)) * DD;
#pragma unroll
        for (int it = 0; it < 32; ++it) {
            int idx = tid + it * 256;      // 0..8191 float4s
            int r = idx >> 7;
            int q = idx & 127;
            float4 v4 = *(const float4*)(Ab + (size_t)r * DD + q * 4);
            uint2 hv;
            hv.x = pack2h(__float2half_rn(v4.x), __float2half_rn(v4.y));
            hv.y = pack2h(__float2half_rn(v4.z), __float2half_rn(v4.w));
            *(uint2*)(sA + r * PADA + q * 4) = hv;
        }
    }

    // ---- B prefetch: chunk (uc,c) -> stage (hi+lo planes) ----
    auto issueB = [&](int uc_, int c_, int stage) {
        const int u0 = uc_ * 128;
        const int k0 = c_ * 32;
#pragma unroll
        for (int j = 0; j < 4; ++j) {
            int op  = tid + j * 256;        // 0..1023
            int arr = op >> 9;              // 0 hi, 1 lo
            int o   = op & 511;
            int row = o >> 2;
            int q   = o & 3;
            const __half* src =
                (arr ? g_wt_lo : g_wt_hi) + (size_t)(u0 + row) * DD + k0 + q * 8;
            __half* dst =
                sB + stage * B_STAGE_H + arr * B_HALF_H + row * PADB + q * 8;
            cp16(dst, src);
        }
        cp_commit();
    };

    float s[4];
#pragma unroll
    for (int i = 0; i < 4; ++i) s[i] = 0.f;

    issueB(0, 0, 0);

    for (int uc = 0; uc < 4; ++uc) {
        __syncthreads();                    // prior epilogue done with hb/vs
        if (tid < 128) {
            hb_s[tid] = g_hb[b * UU + uc * 128 + tid];
            vs_s[tid] = V[uc * 128 + tid];
        }

        float acc[32];
#pragma unroll
        for (int i = 0; i < 32; ++i) acc[i] = 0.f;

        for (int c = 0; c < 16; ++c) {
            const int gc = uc * 16 + c;
            const int stage = gc & 1;
            if (gc < 63) {
                int nuc = (c == 15) ? uc + 1 : uc;
                int nc  = (c == 15) ? 0 : c + 1;
                issueB(nuc, nc, (gc + 1) & 1);
                cp_wait1();
            } else {
                cp_wait0();
            }
            __syncthreads();

            const __half* Bh = sB + stage * B_STAGE_H;
            const __half* Bl = Bh + B_HALF_H;
            const int k0 = c * 32;
#pragma unroll
            for (int kk = 0; kk < 32; kk += 16) {
                unsigned bh[8], bl[8];
#pragma unroll
                for (int p = 0; p < 2; ++p) {
                    ldm4(bh + 4 * p, Bh + (nbase + p * 16) * PADB + kk + b_lane_off);
                    ldm4(bl + 4 * p, Bl + (nbase + p * 16) * PADB + kk + b_lane_off);
                }
#pragma unroll
                for (int mt = 0; mt < 2; ++mt) {
                    unsigned ah[4];
                    ldm4(ah, sA + (mbase + mt * 16) * PADA + k0 + kk + a_lane_off);
#pragma unroll
                    for (int nt = 0; nt < 4; ++nt) {
                        float* cc = acc + (mt * 4 + nt) * 4;
                        mma16816(cc, ah, bh + 2 * nt);
                        mma16816(cc, ah, bl + 2 * nt);
                    }
                }
            }
            __syncthreads();                // buffer reuse safety
        }

        // ---- epilogue for this u-chunk ----
#pragma unroll
        for (int mt = 0; mt < 2; ++mt) {
#pragma unroll
            for (int nt = 0; nt < 4; ++nt) {
                const float* cc = acc + (mt * 4 + nt) * 4;
                int n0 = nbase + nt * 8 + 2 * t;
                s[mt * 2 + 0] += fast_tanh(cc[0] + hb_s[n0]) * vs_s[n0]
                               + fast_tanh(cc[1] + hb_s[n0 + 1]) * vs_s[n0 + 1];
                s[mt * 2 + 1] += fast_tanh(cc[2] + hb_s[n0]) * vs_s[n0]
                               + fast_tanh(cc[3] + hb_s[n0 + 1]) * vs_s[n0 + 1];
            }
        }
    }

    // ---- reduce over t lanes (width 4), then 4 nw-warps via smem ----
#pragma unroll
    for (int i = 0; i < 4; ++i) {
        float v = s[i];
        v += __shfl_xor_sync(0xffffffffu, v, 1, 4);
        v += __shfl_xor_sync(0xffffffffu, v, 2, 4);
        if (t == 0) {
            int mt = i >> 1, half = i & 1;
            int row = mbase + mt * 16 + half * 8 + g;
            red[nw * 64 + row] = v;
        }
    }
    __syncthreads();
    if (tid < 64) {
        float sum = red[tid] + red[64 + tid] + red[128 + tid] + red[192 + tid];
        g_scores[b * TT + t0 + tid] = sum + bV[0];
    }
}

// ---------------------------------------------------------------------------
// Kernel 3: softmax stats (single pass, scores in registers)
// ---------------------------------------------------------------------------
__global__ void k_stats() {
    int b = blockIdx.x;
    int tid = threadIdx.x;   // 256
    __shared__ float red[256];

    float v[8];
    const float4* sp = (const float4*)(g_scores + b * TT) + tid * 2;
    float4 a0 = sp[0], a1 = sp[1];
    v[0] = a0.x; v[1] = a0.y; v[2] = a0.z; v[3] = a0.w;
    v[4] = a1.x; v[5] = a1.y; v[6] = a1.z; v[7] = a1.w;

    float m = -INFINITY;
#pragma unroll
    for (int i = 0; i < 8; ++i) m = fmaxf(m, v[i]);
    red[tid] = m;
    __syncthreads();
    for (int sft = 128; sft > 0; sft >>= 1) {
        if (tid < sft) red[tid] = fmaxf(red[tid], red[tid + sft]);
        __syncthreads();
    }
    m = red[0];
    __syncthreads();

    float z = 0.f;
#pragma unroll
    for (int i = 0; i < 8; ++i) z += expf(v[i] - m);
    red[tid] = z;
    __syncthreads();
    for (int sft = 128; sft > 0; sft >>= 1) {
        if (tid < sft) red[tid] += red[tid + sft];
        __syncthreads();
    }
    if (tid == 0) { g_m[b] = m; g_z[b] = red[0]; }
}

// ---------------------------------------------------------------------------
// Kernel 4: partial weighted sums
// ---------------------------------------------------------------------------
__global__ __launch_bounds__(128) void k_context(const float* __restrict__ full) {
    int b  = blockIdx.y;
    int tc = blockIdx.x;
    int tid = threadIdx.x;
    __shared__ float ws[TCHUNK];

    float m = g_m[b];
    if (tid < TCHUNK)
        ws[tid] = expf(g_scores[b * TT + tc * TCHUNK + tid] - m);
    __syncthreads();

    const float4* fp =
        (const float4*)(full + ((size_t)(b * TT + tc * TCHUNK)) * DD) + tid;
    float4 acc = make_float4(0.f, 0.f, 0.f, 0.f);
#pragma unroll 8
    for (int t = 0; t < TCHUNK; ++t) {
        float4 f = fp[(size_t)t * (DD / 4)];
        float w = ws[t];
        acc.x += w * f.x;
        acc.y += w * f.y;
        acc.z += w * f.z;
        acc.w += w * f.w;
    }
    float4* pp = (float4*)(g_part + ((size_t)(b * TCH + tc)) * DD) + tid;
    *pp = acc;
}

// ---------------------------------------------------------------------------
// Kernel 5: combine partials
// ---------------------------------------------------------------------------
__global__ void k_combine(float* __restrict__ out) {
    int idx = blockIdx.x * 256 + threadIdx.x;
    if (idx >= BB * DD) return;
    int b = idx / DD;
    int d = idx - b * DD;
    float acc = 0.f;
#pragma unroll
    for (int tc = 0; tc < TCH; ++tc)
        acc += g_part[((size_t)(b * TCH + tc)) * DD + d];
    out[idx] = acc / g_z[b];
}

// ---------------------------------------------------------------------------
extern "C" void kernel_launch(void* const* d_in, const int* in_sizes, int n_in,
                              void* d_out, int out_size) {
    const float* full = (const float*)d_in[0];
    const float* last = (const float*)d_in[1];
    const float* W1   = (const float*)d_in[2];
    const float* b1   = (const float*)d_in[3];
    const float* W2   = (const float*)d_in[4];
    const float* b2   = (const float*)d_in[5];
    const float* V    = (const float*)d_in[6];
    const float* bV   = (const float*)d_in[7];
    float* out = (float*)d_out;

    cudaFuncSetAttribute(k_score, cudaFuncAttributeMaxDynamicSharedMemorySize,
                         SMEM_TOTAL);

    k_prep<<<DD, UU>>>(W1);
    k_h2<<<BB, DD>>>(last, W2, b1, b2);

    dim3 gScore(TT / 64, BB);
    k_score<<<gScore, 256, SMEM_TOTAL>>>(full, V, bV);

    k_stats<<<BB, 256>>>();

    dim3 gCtx(TCH, BB);
    k_context<<<gCtx, 128>>>(full);

    k_combine<<<(BB * DD + 255) / 256, 256>>>(out);
}

// round 6
// speedup vs baseline: 2.1960x; 1.5833x over previous
#include <cuda_runtime.h>
#include <cuda_fp16.h>
#include <cstdint>
#include <math.h>

#define BB 32
#define TT 2048
#define DD 512
#define UU 512

#define TCH 32
#define TCHUNK (TT / TCH)   // 64

// ---- scratch ----
__device__ float g_hb[BB * UU];
__device__ float g_scores[BB * TT];
__device__ float g_m[BB];
__device__ float g_z[BB];
__device__ float g_part[BB * TCH * DD];
__device__ __half g_wt[UU * DD];         // W1^T fp16 [u][d]

// ---------------- helpers ----------------
static __device__ __forceinline__ unsigned pack2h(__half a, __half b) {
    return (unsigned)__half_as_ushort(a) |
           ((unsigned)__half_as_ushort(b) << 16);
}
static __device__ __forceinline__ float fast_tanh(float x) {
    float e = __expf(2.f * x);
    return 1.f - __fdividef(2.f, e + 1.f);
}
static __device__ __forceinline__ void mma16816(float* c, const unsigned* a, const unsigned* b) {
    asm volatile(
        "mma.sync.aligned.m16n8k16.row.col.f32.f16.f16.f32 "
        "{%0,%1,%2,%3}, {%4,%5,%6,%7}, {%8,%9}, {%0,%1,%2,%3};"
        : "+f"(c[0]), "+f"(c[1]), "+f"(c[2]), "+f"(c[3])
        : "r"(a[0]), "r"(a[1]), "r"(a[2]), "r"(a[3]), "r"(b[0]), "r"(b[1]));
}
static __device__ __forceinline__ void ldm4(unsigned* r, const void* p) {
    unsigned addr = (unsigned)__cvta_generic_to_shared(p);
    asm volatile(
        "ldmatrix.sync.aligned.m8n8.x4.shared.b16 {%0,%1,%2,%3}, [%4];"
        : "=r"(r[0]), "=r"(r[1]), "=r"(r[2]), "=r"(r[3])
        : "r"(addr));
}
static __device__ __forceinline__ void cp16(void* dst, const void* src) {
    unsigned d = (unsigned)__cvta_generic_to_shared(dst);
    asm volatile("cp.async.cg.shared.global [%0], [%1], 16;"
                 :: "r"(d), "l"(src) : "memory");
}
static __device__ __forceinline__ void cp_commit() {
    asm volatile("cp.async.commit_group;" ::: "memory");
}
static __device__ __forceinline__ void cp_wait1() {
    asm volatile("cp.async.wait_group 1;" ::: "memory");
}
static __device__ __forceinline__ void cp_wait0() {
    asm volatile("cp.async.wait_group 0;" ::: "memory");
}

// smem layout
#define PADA 520                            // A row stride (halves)
#define PADB 40                             // B row stride (halves)
#define OFF_HB   0
#define OFF_VS   512
#define OFF_RED  1024
#define OFF_B    2048
#define B_STAGE_H (128 * PADB)              // one plane per stage (halves) = 5120
#define OFF_A    (OFF_B + 2 * B_STAGE_H * 2)   // 2048 + 20480 = 22528
#define SMEM_TOTAL (OFF_A + 64 * PADA * 2)     // 22528 + 66560 = 89088

// ---------------------------------------------------------------------------
// Kernel 0: transpose W1 -> fp16 [u][d]
// ---------------------------------------------------------------------------
__global__ void k_prep(const float* __restrict__ W1) {
    int d = blockIdx.x;
    int u = threadIdx.x;
    g_wt[u * DD + d] = __float2half_rn(W1[d * UU + u]);
}

// ---------------------------------------------------------------------------
// Kernel 1: g_hb[b,u] = last[b,:] @ W2[:,u] + b1[u] + b2[u]   (fp32)
// ---------------------------------------------------------------------------
__global__ void k_h2(const float* __restrict__ last, const float* __restrict__ W2,
                     const float* __restrict__ b1, const float* __restrict__ b2) {
    int b = blockIdx.x;
    int u = threadIdx.x;
    __shared__ float sl[DD];
    sl[u] = last[b * DD + u];
    __syncthreads();
    float acc = 0.f;
#pragma unroll 8
    for (int d = 0; d < DD; ++d)
        acc += sl[d] * W2[d * UU + u];
    g_hb[b * UU + u] = acc + b1[u] + b2[u];
}

// ---------------------------------------------------------------------------
// Kernel 2: scores. CTA = 64t x 512u(4 passes) x 512k.
// A: fp16, converted once, resident in smem.  B: W1^T fp16 streamed via
// cp.async double buffer.  1-term mma.sync.  Fused tanh/V epilogue.
// ---------------------------------------------------------------------------
__global__ __launch_bounds__(256, 2) void k_score(
    const float* __restrict__ full,
    const float* __restrict__ V, const float* __restrict__ bV) {
    extern __shared__ __align__(16) char smem[];
    float* hb_s = (float*)(smem + OFF_HB);
    float* vs_s = (float*)(smem + OFF_VS);
    float* red  = (float*)(smem + OFF_RED);
    __half* sB  = (__half*)(smem + OFF_B);
    __half* sA  = (__half*)(smem + OFF_A);

    const int tid = threadIdx.x;
    const int wid = tid >> 5;
    const int lane = tid & 31;
    const int g = lane >> 2;
    const int t = lane & 3;
    const int mw = wid >> 2;        // 0..1
    const int nw = wid & 3;         // 0..3
    const int mbase = mw * 32;
    const int nbase = nw * 32;

    const int b  = blockIdx.y;
    const int t0 = blockIdx.x * 64;

    const int tile = lane >> 3;
    const int rr = lane & 7;
    const int a_lane_off = ((tile & 1) * 8 + rr) * PADA + ((tile >> 1) & 1) * 8;
    const int b_lane_off = (((tile >> 1) & 1) * 8 + rr) * PADB + (tile & 1) * 8;

    // ---- convert A tile (64 x 512 fp32 -> fp16), resident ----
    {
        const float* Ab = full + ((size_t)(b * TT + t0)) * DD;
#pragma unroll
        for (int it = 0; it < 32; ++it) {
            int idx = tid + it * 256;      // 0..8191 float4s
            int r = idx >> 7;
            int q = idx & 127;
            float4 v4 = *(const float4*)(Ab + (size_t)r * DD + q * 4);
            uint2 hv;
            hv.x = pack2h(__float2half_rn(v4.x), __float2half_rn(v4.y));
            hv.y = pack2h(__float2half_rn(v4.z), __float2half_rn(v4.w));
            *(uint2*)(sA + r * PADA + q * 4) = hv;
        }
    }

    // ---- B prefetch: chunk (uc,c) -> stage (single plane, 8 KB) ----
    auto issueB = [&](int uc_, int c_, int stage) {
        const int u0 = uc_ * 128;
        const int k0 = c_ * 32;
#pragma unroll
        for (int j = 0; j < 2; ++j) {
            int o   = tid + j * 256;        // 0..511
            int row = o >> 2;
            int q   = o & 3;
            const __half* src = g_wt + (size_t)(u0 + row) * DD + k0 + q * 8;
            __half* dst = sB + stage * B_STAGE_H + row * PADB + q * 8;
            cp16(dst, src);
        }
        cp_commit();
    };

    float s[4];
#pragma unroll
    for (int i = 0; i < 4; ++i) s[i] = 0.f;

    issueB(0, 0, 0);

    for (int uc = 0; uc < 4; ++uc) {
        __syncthreads();                    // prior epilogue done with hb/vs
        if (tid < 128) {
            hb_s[tid] = g_hb[b * UU + uc * 128 + tid];
            vs_s[tid] = V[uc * 128 + tid];
        }

        float acc[32];
#pragma unroll
        for (int i = 0; i < 32; ++i) acc[i] = 0.f;

        for (int c = 0; c < 16; ++c) {
            const int gc = uc * 16 + c;
            const int stage = gc & 1;
            if (gc < 63) {
                int nuc = (c == 15) ? uc + 1 : uc;
                int nc  = (c == 15) ? 0 : c + 1;
                issueB(nuc, nc, (gc + 1) & 1);
                cp_wait1();
            } else {
                cp_wait0();
            }
            __syncthreads();

            const __half* Bh = sB + stage * B_STAGE_H;
            const int k0 = c * 32;
#pragma unroll
            for (int kk = 0; kk < 32; kk += 16) {
                unsigned bh[8];
#pragma unroll
                for (int p = 0; p < 2; ++p)
                    ldm4(bh + 4 * p, Bh + (nbase + p * 16) * PADB + kk + b_lane_off);
#pragma unroll
                for (int mt = 0; mt < 2; ++mt) {
                    unsigned ah[4];
                    ldm4(ah, sA + (mbase + mt * 16) * PADA + k0 + kk + a_lane_off);
#pragma unroll
                    for (int nt = 0; nt < 4; ++nt)
                        mma16816(acc + (mt * 4 + nt) * 4, ah, bh + 2 * nt);
                }
            }
            __syncthreads();                // buffer reuse safety
        }

        // ---- epilogue for this u-chunk ----
#pragma unroll
        for (int mt = 0; mt < 2; ++mt) {
#pragma unroll
            for (int nt = 0; nt < 4; ++nt) {
                const float* cc = acc + (mt * 4 + nt) * 4;
                int n0 = nbase + nt * 8 + 2 * t;
                s[mt * 2 + 0] += fast_tanh(cc[0] + hb_s[n0]) * vs_s[n0]
                               + fast_tanh(cc[1] + hb_s[n0 + 1]) * vs_s[n0 + 1];
                s[mt * 2 + 1] += fast_tanh(cc[2] + hb_s[n0]) * vs_s[n0]
                               + fast_tanh(cc[3] + hb_s[n0 + 1]) * vs_s[n0 + 1];
            }
        }
    }

    // ---- reduce over t lanes (width 4), then 4 nw-warps via smem ----
#pragma unroll
    for (int i = 0; i < 4; ++i) {
        float v = s[i];
        v += __shfl_xor_sync(0xffffffffu, v, 1, 4);
        v += __shfl_xor_sync(0xffffffffu, v, 2, 4);
        if (t == 0) {
            int mt = i >> 1, half = i & 1;
            int row = mbase + mt * 16 + half * 8 + g;
            red[nw * 64 + row] = v;
        }
    }
    __syncthreads();
    if (tid < 64) {
        float sum = red[tid] + red[64 + tid] + red[128 + tid] + red[192 + tid];
        g_scores[b * TT + t0 + tid] = sum + bV[0];
    }
}

// ---------------------------------------------------------------------------
// Kernel 3: softmax stats (single pass, scores in registers)
// ---------------------------------------------------------------------------
__global__ void k_stats() {
    int b = blockIdx.x;
    int tid = threadIdx.x;   // 256
    __shared__ float red[256];

    float v[8];
    const float4* sp = (const float4*)(g_scores + b * TT) + tid * 2;
    float4 a0 = sp[0], a1 = sp[1];
    v[0] = a0.x; v[1] = a0.y; v[2] = a0.z; v[3] = a0.w;
    v[4] = a1.x; v[5] = a1.y; v[6] = a1.z; v[7] = a1.w;

    float m = -INFINITY;
#pragma unroll
    for (int i = 0; i < 8; ++i) m = fmaxf(m, v[i]);
    red[tid] = m;
    __syncthreads();
    for (int sft = 128; sft > 0; sft >>= 1) {
        if (tid < sft) red[tid] = fmaxf(red[tid], red[tid + sft]);
        __syncthreads();
    }
    m = red[0];
    __syncthreads();

    float z = 0.f;
#pragma unroll
    for (int i = 0; i < 8; ++i) z += expf(v[i] - m);
    red[tid] = z;
    __syncthreads();
    for (int sft = 128; sft > 0; sft >>= 1) {
        if (tid < sft) red[tid] += red[tid + sft];
        __syncthreads();
    }
    if (tid == 0) { g_m[b] = m; g_z[b] = red[0]; }
}

// ---------------------------------------------------------------------------
// Kernel 4: partial weighted sums
// ---------------------------------------------------------------------------
__global__ __launch_bounds__(128) void k_context(const float* __restrict__ full) {
    int b  = blockIdx.y;
    int tc = blockIdx.x;
    int tid = threadIdx.x;
    __shared__ float ws[TCHUNK];

    float m = g_m[b];
    if (tid < TCHUNK)
        ws[tid] = expf(g_scores[b * TT + tc * TCHUNK + tid] - m);
    __syncthreads();

    const float4* fp =
        (const float4*)(full + ((size_t)(b * TT + tc * TCHUNK)) * DD) + tid;
    float4 acc = make_float4(0.f, 0.f, 0.f, 0.f);
#pragma unroll 8
    for (int t = 0; t < TCHUNK; ++t) {
        float4 f = fp[(size_t)t * (DD / 4)];
        float w = ws[t];
        acc.x += w * f.x;
        acc.y += w * f.y;
        acc.z += w * f.z;
        acc.w += w * f.w;
    }
    float4* pp = (float4*)(g_part + ((size_t)(b * TCH + tc)) * DD) + tid;
    *pp = acc;
}

// ---------------------------------------------------------------------------
// Kernel 5: combine partials
// ---------------------------------------------------------------------------
__global__ void k_combine(float* __restrict__ out) {
    int idx = blockIdx.x * 256 + threadIdx.x;
    if (idx >= BB * DD) return;
    int b = idx / DD;
    int d = idx - b * DD;
    float acc = 0.f;
#pragma unroll
    for (int tc = 0; tc < TCH; ++tc)
        acc += g_part[((size_t)(b * TCH + tc)) * DD + d];
    out[idx] = acc / g_z[b];
}

// ---------------------------------------------------------------------------
extern "C" void kernel_launch(void* const* d_in, const int* in_sizes, int n_in,
                              void* d_out, int out_size) {
    const float* full = (const float*)d_in[0];
    const float* last = (const float*)d_in[1];
    const float* W1   = (const float*)d_in[2];
    const float* b1   = (const float*)d_in[3];
    const float* W2   = (const float*)d_in[4];
    const float* b2   = (const float*)d_in[5];
    const float* V    = (const float*)d_in[6];
    const float* bV   = (const float*)d_in[7];
    float* out = (float*)d_out;

    cudaFuncSetAttribute(k_score, cudaFuncAttributeMaxDynamicSharedMemorySize,
                         SMEM_TOTAL);

    k_prep<<<DD, UU>>>(W1);
    k_h2<<<BB, DD>>>(last, W2, b1, b2);

    dim3 gScore(TT / 64, BB);
    k_score<<<gScore, 256, SMEM_TOTAL>>>(full, V, bV);

    k_stats<<<BB, 256>>>();

    dim3 gCtx(TCH, BB);
    k_context<<<gCtx, 128>>>(full);

    k_combine<<<(BB * DD + 255) / 256, 256>>>(out);
}

// round 7
// speedup vs baseline: 2.2657x; 1.0317x over previous
#include <cuda_runtime.h>
#include <cuda_fp16.h>
#include <cstdint>
#include <math.h>

#define BB 32
#define TT 2048
#define DD 512
#define UU 512

#define TCH 32
#define TCHUNK (TT / TCH)   // 64

// ---- scratch ----
__device__ float g_hb[BB * UU];
__device__ float g_scores[BB * TT];
__device__ float g_zpart[BB * TCH];
__device__ float g_part[BB * TCH * DD];
__device__ __half g_wt[UU * DD];         // W1^T fp16 [u][d]

// ---------------- helpers ----------------
static __device__ __forceinline__ unsigned pack2h(__half a, __half b) {
    return (unsigned)__half_as_ushort(a) |
           ((unsigned)__half_as_ushort(b) << 16);
}
static __device__ __forceinline__ float fast_tanh(float x) {
    float e = __expf(2.f * x);
    return 1.f - __fdividef(2.f, e + 1.f);
}
static __device__ __forceinline__ void mma16816(float* c, const unsigned* a, const unsigned* b) {
    asm volatile(
        "mma.sync.aligned.m16n8k16.row.col.f32.f16.f16.f32 "
        "{%0,%1,%2,%3}, {%4,%5,%6,%7}, {%8,%9}, {%0,%1,%2,%3};"
        : "+f"(c[0]), "+f"(c[1]), "+f"(c[2]), "+f"(c[3])
        : "r"(a[0]), "r"(a[1]), "r"(a[2]), "r"(a[3]), "r"(b[0]), "r"(b[1]));
}
static __device__ __forceinline__ void ldm4(unsigned* r, const void* p) {
    unsigned addr = (unsigned)__cvta_generic_to_shared(p);
    asm volatile(
        "ldmatrix.sync.aligned.m8n8.x4.shared.b16 {%0,%1,%2,%3}, [%4];"
        : "=r"(r[0]), "=r"(r[1]), "=r"(r[2]), "=r"(r[3])
        : "r"(addr));
}
static __device__ __forceinline__ void cp16(void* dst, const void* src) {
    unsigned d = (unsigned)__cvta_generic_to_shared(dst);
    asm volatile("cp.async.cg.shared.global [%0], [%1], 16;"
                 :: "r"(d), "l"(src) : "memory");
}
static __device__ __forceinline__ void cp_commit() {
    asm volatile("cp.async.commit_group;" ::: "memory");
}
static __device__ __forceinline__ void cp_wait2() {
    asm volatile("cp.async.wait_group 2;" ::: "memory");
}
static __device__ __forceinline__ void cp_wait1() {
    asm volatile("cp.async.wait_group 1;" ::: "memory");
}
static __device__ __forceinline__ void cp_wait0() {
    asm volatile("cp.async.wait_group 0;" ::: "memory");
}

// smem layout (halves unless noted)
#define PADA 520
#define PADB 40
#define NSTAGE 4
#define OFF_HB   0
#define OFF_VS   512
#define OFF_RED  1024
#define OFF_B    2048
#define B_STAGE_H (128 * PADB)                         // 5120 halves = 10 KB
#define OFF_A    (OFF_B + NSTAGE * B_STAGE_H * 2)      // 2048 + 40960 = 43008
#define SMEM_TOTAL (OFF_A + 64 * PADA * 2)             // 109568 B

// ---------------------------------------------------------------------------
// Kernel A: fused W1 transpose->fp16  +  h2 precompute
// grid 544 x 512 threads.  bid<512: prep row d=bid.  bid>=512: h2 for batch.
// ---------------------------------------------------------------------------
__global__ void k_prep_h2(const float* __restrict__ W1,
                          const float* __restrict__ last,
                          const float* __restrict__ W2,
                          const float* __restrict__ b1,
                          const float* __restrict__ b2) {
    if (blockIdx.x < 512) {
        int d = blockIdx.x;
        int u = threadIdx.x;
        g_wt[u * DD + d] = __float2half_rn(W1[d * UU + u]);
    } else {
        int b = blockIdx.x - 512;
        int u = threadIdx.x;
        __shared__ float sl[DD];
        sl[u] = last[b * DD + u];
        __syncthreads();
        float acc = 0.f;
#pragma unroll 8
        for (int d = 0; d < DD; ++d)
            acc += sl[d] * W2[d * UU + u];
        g_hb[b * UU + u] = acc + b1[u] + b2[u];
    }
}

// ---------------------------------------------------------------------------
// Kernel B: scores.  CTA = 64t x 512u(4 passes) x 512k.  A fp16 resident;
// B streamed via 4-stage cp.async ring, ONE barrier per k-chunk.
// ---------------------------------------------------------------------------
__global__ __launch_bounds__(256, 2) void k_score(
    const float* __restrict__ full, const float* __restrict__ V) {
    extern __shared__ __align__(16) char smem[];
    float* hb_s = (float*)(smem + OFF_HB);
    float* vs_s = (float*)(smem + OFF_VS);
    float* red  = (float*)(smem + OFF_RED);
    __half* sB  = (__half*)(smem + OFF_B);
    __half* sA  = (__half*)(smem + OFF_A);

    const int tid = threadIdx.x;
    const int wid = tid >> 5;
    const int lane = tid & 31;
    const int g = lane >> 2;
    const int t = lane & 3;
    const int mw = wid >> 2;
    const int nw = wid & 3;
    const int mbase = mw * 32;
    const int nbase = nw * 32;

    const int b  = blockIdx.y;
    const int t0 = blockIdx.x * 64;

    const int tile = lane >> 3;
    const int rr = lane & 7;
    const int a_lane_off = ((tile & 1) * 8 + rr) * PADA + ((tile >> 1) & 1) * 8;
    const int b_lane_off = (((tile >> 1) & 1) * 8 + rr) * PADB + (tile & 1) * 8;

    // ---- B prefetch: global chunk gc (uc = gc>>4, kc = gc&15) -> slot ----
    auto issueB = [&](int gc, int slot) {
        const int u0 = (gc >> 4) * 128;
        const int k0 = (gc & 15) * 32;
#pragma unroll
        for (int j = 0; j < 2; ++j) {
            int o   = tid + j * 256;        // 0..511
            int row = o >> 2;
            int q   = o & 3;
            const __half* src = g_wt + (size_t)(u0 + row) * DD + k0 + q * 8;
            __half* dst = sB + slot * B_STAGE_H + row * PADB + q * 8;
            cp16(dst, src);
        }
        cp_commit();
    };

    // prologue: 3 chunks in flight, then convert A (overlaps with cp.async)
    issueB(0, 0);
    issueB(1, 1);
    issueB(2, 2);

    {
        const float* Ab = full + ((size_t)(b * TT + t0)) * DD;
#pragma unroll
        for (int it = 0; it < 32; ++it) {
            int idx = tid + it * 256;
            int r = idx >> 7;
            int q = idx & 127;
            float4 v4 = *(const float4*)(Ab + (size_t)r * DD + q * 4);
            uint2 hv;
            hv.x = pack2h(__float2half_rn(v4.x), __float2half_rn(v4.y));
            hv.y = pack2h(__float2half_rn(v4.z), __float2half_rn(v4.w));
            *(uint2*)(sA + r * PADA + q * 4) = hv;
        }
    }

    float s[4];
#pragma unroll
    for (int i = 0; i < 4; ++i) s[i] = 0.f;
    float acc[32];

    for (int gc = 0; gc < 64; ++gc) {
        const int slot = gc & 3;
        // chunk gc's group complete (pending <= 2 most recent)
        if (gc <= 61) cp_wait2();
        else if (gc == 62) cp_wait1();
        else cp_wait0();
        __syncthreads();   // data visible; all warps past compute gc-1 & epilogue

        if ((gc & 15) == 0) {
            int uc = gc >> 4;
            if (tid < 128) {
                hb_s[tid] = g_hb[b * UU + uc * 128 + tid];
                vs_s[tid] = V[uc * 128 + tid];
            }
#pragma unroll
            for (int i = 0; i < 32; ++i) acc[i] = 0.f;
        }
        if (gc + 3 < 64) issueB(gc + 3, (gc + 3) & 3);

        const __half* Bh = sB + slot * B_STAGE_H;
        const int k0 = (gc & 15) * 32;
#pragma unroll
        for (int kk = 0; kk < 32; kk += 16) {
            unsigned bh[8];
#pragma unroll
            for (int p = 0; p < 2; ++p)
                ldm4(bh + 4 * p, Bh + (nbase + p * 16) * PADB + kk + b_lane_off);
#pragma unroll
            for (int mt = 0; mt < 2; ++mt) {
                unsigned ah[4];
                ldm4(ah, sA + (mbase + mt * 16) * PADA + k0 + kk + a_lane_off);
#pragma unroll
                for (int nt = 0; nt < 4; ++nt)
                    mma16816(acc + (mt * 4 + nt) * 4, ah, bh + 2 * nt);
            }
        }

        if ((gc & 15) == 15) {
            // epilogue for this u-chunk (before next iter's barrier)
#pragma unroll
            for (int mt = 0; mt < 2; ++mt) {
#pragma unroll
                for (int nt = 0; nt < 4; ++nt) {
                    const float* cc = acc + (mt * 4 + nt) * 4;
                    int n0 = nbase + nt * 8 + 2 * t;
                    s[mt * 2 + 0] += fast_tanh(cc[0] + hb_s[n0]) * vs_s[n0]
                                   + fast_tanh(cc[1] + hb_s[n0 + 1]) * vs_s[n0 + 1];
                    s[mt * 2 + 1] += fast_tanh(cc[2] + hb_s[n0]) * vs_s[n0]
                                   + fast_tanh(cc[3] + hb_s[n0 + 1]) * vs_s[n0 + 1];
                }
            }
        }
    }

    // ---- reduce over t lanes (width 4), then 4 nw-warps via smem ----
#pragma unroll
    for (int i = 0; i < 4; ++i) {
        float v = s[i];
        v += __shfl_xor_sync(0xffffffffu, v, 1, 4);
        v += __shfl_xor_sync(0xffffffffu, v, 2, 4);
        if (t == 0) {
            int mt = i >> 1, half = i & 1;
            int row = mbase + mt * 16 + half * 8 + g;
            red[nw * 64 + row] = v;
        }
    }
    __syncthreads();
    if (tid < 64) {
        float sum = red[tid] + red[64 + tid] + red[128 + tid] + red[192 + tid];
        g_scores[b * TT + t0 + tid] = sum;     // bV dropped: cancels in softmax
    }
}

// ---------------------------------------------------------------------------
// Kernel C: partial weighted sums + partial Z (no max subtraction needed:
// scores are O(1), exp cannot overflow fp32)
// ---------------------------------------------------------------------------
__global__ __launch_bounds__(256) void k_context(const float* __restrict__ full) {
    int b  = blockIdx.y;
    int tc = blockIdx.x;
    int tid = threadIdx.x;
    __shared__ float ws[TCHUNK];
    __shared__ float4 tmp[128];

    if (tid < TCHUNK)
        ws[tid] = expf(g_scores[b * TT + tc * TCHUNK + tid]);
    __syncthreads();

    if (tid == 0) {
        float z = 0.f;
#pragma unroll
        for (int i = 0; i < TCHUNK; ++i) z += ws[i];
        g_zpart[b * TCH + tc] = z;
    }

    int ro = tid >> 7;          // 0/1: two rows in flight
    int d4 = tid & 127;
    const float4* fp =
        (const float4*)(full + ((size_t)(b * TT + tc * TCHUNK)) * DD);
    float4 acc = make_float4(0.f, 0.f, 0.f, 0.f);
#pragma unroll 8
    for (int t = 0; t < TCHUNK; t += 2) {
        float4 f = fp[(size_t)(t + ro) * (DD / 4) + d4];
        float w = ws[t + ro];
        acc.x += w * f.x;
        acc.y += w * f.y;
        acc.z += w * f.z;
        acc.w += w * f.w;
    }
    if (ro == 1) tmp[d4] = acc;
    __syncthreads();
    if (ro == 0) {
        float4 o = tmp[d4];
        acc.x += o.x; acc.y += o.y; acc.z += o.z; acc.w += o.w;
        ((float4*)(g_part + ((size_t)(b * TCH + tc)) * DD))[d4] = acc;
    }
}

// ---------------------------------------------------------------------------
// Kernel D: combine partials + Z, divide
// ---------------------------------------------------------------------------
__global__ void k_combine(float* __restrict__ out) {
    int b = blockIdx.x;
    int d = threadIdx.x;       // 512
    __shared__ float zs;
    if (d == 0) {
        float z = 0.f;
#pragma unroll
        for (int tc = 0; tc < TCH; ++tc) z += g_zpart[b * TCH + tc];
        zs = z;
    }
    __syncthreads();
    float acc = 0.f;
#pragma unroll
    for (int tc = 0; tc < TCH; ++tc)
        acc += g_part[((size_t)(b * TCH + tc)) * DD + d];
    out[b * DD + d] = acc / zs;
}

// ---------------------------------------------------------------------------
extern "C" void kernel_launch(void* const* d_in, const int* in_sizes, int n_in,
                              void* d_out, int out_size) {
    const float* full = (const float*)d_in[0];
    const float* last = (const float*)d_in[1];
    const float* W1   = (const float*)d_in[2];
    const float* b1   = (const float*)d_in[3];
    const float* W2   = (const float*)d_in[4];
    const float* b2   = (const float*)d_in[5];
    const float* V    = (const float*)d_in[6];
    float* out = (float*)d_out;

    cudaFuncSetAttribute(k_score, cudaFuncAttributeMaxDynamicSharedMemorySize,
                         SMEM_TOTAL);

    k_prep_h2<<<544, 512>>>(W1, last, W2, b1, b2);

    dim3 gScore(TT / 64, BB);
    k_score<<<gScore, 256, SMEM_TOTAL>>>(full, V);

    dim3 gCtx(TCH, BB);
    k_context<<<gCtx, 256>>>(full);

    k_combine<<<BB, DD>>>(out);
}

// round 9
// speedup vs baseline: 2.3828x; 1.0517x over previous
#include <cuda_runtime.h>
#include <cuda_fp16.h>
#include <cstdint>
#include <math.h>

#define BB 32
#define TT 2048
#define DD 512
#define UU 512

#define TCH 32                 // t-chunks per batch (= grid.x of k_score)

// ---- scratch ----
__device__ float g_hb[BB * UU];
__device__ float g_zpart[BB * TCH];
__device__ float g_part[BB * TCH * DD];
__device__ __half g_wt[UU * DD];         // W1^T fp16 [u][d]

// ---------------- helpers ----------------
static __device__ __forceinline__ unsigned pack2h(__half a, __half b) {
    return (unsigned)__half_as_ushort(a) |
           ((unsigned)__half_as_ushort(b) << 16);
}
static __device__ __forceinline__ float fast_tanh(float x) {
    float e = __expf(2.f * x);
    return 1.f - __fdividef(2.f, e + 1.f);
}
static __device__ __forceinline__ void mma16816(float* c, const unsigned* a, const unsigned* b) {
    asm volatile(
        "mma.sync.aligned.m16n8k16.row.col.f32.f16.f16.f32 "
        "{%0,%1,%2,%3}, {%4,%5,%6,%7}, {%8,%9}, {%0,%1,%2,%3};"
        : "+f"(c[0]), "+f"(c[1]), "+f"(c[2]), "+f"(c[3])
        : "r"(a[0]), "r"(a[1]), "r"(a[2]), "r"(a[3]), "r"(b[0]), "r"(b[1]));
}
static __device__ __forceinline__ void ldm4(unsigned* r, const void* p) {
    unsigned addr = (unsigned)__cvta_generic_to_shared(p);
    asm volatile(
        "ldmatrix.sync.aligned.m8n8.x4.shared.b16 {%0,%1,%2,%3}, [%4];"
        : "=r"(r[0]), "=r"(r[1]), "=r"(r[2]), "=r"(r[3])
        : "r"(addr));
}
static __device__ __forceinline__ void cp16(void* dst, const void* src) {
    unsigned d = (unsigned)__cvta_generic_to_shared(dst);
    asm volatile("cp.async.cg.shared.global [%0], [%1], 16;"
                 :: "r"(d), "l"(src) : "memory");
}
static __device__ __forceinline__ void cp_commit() {
    asm volatile("cp.async.commit_group;" ::: "memory");
}
static __device__ __forceinline__ void cp_wait2() {
    asm volatile("cp.async.wait_group 2;" ::: "memory");
}
static __device__ __forceinline__ void cp_wait1() {
    asm volatile("cp.async.wait_group 1;" ::: "memory");
}
static __device__ __forceinline__ void cp_wait0() {
    asm volatile("cp.async.wait_group 0;" ::: "memory");
}

// smem layout (halves unless noted)
#define PADA 520
#define PADB 40
#define NSTAGE 4
#define OFF_HB   0
#define OFF_VS   512
#define OFF_RED  1024
#define OFF_B    2048
#define B_STAGE_H (128 * PADB)                         // 5120 halves = 10 KB
#define OFF_A    (OFF_B + NSTAGE * B_STAGE_H * 2)      // 43008
#define SMEM_TOTAL (OFF_A + 64 * PADA * 2)             // 109568 B

// ---------------------------------------------------------------------------
// Kernel A: fused W1 transpose->fp16  +  h2 precompute
// ---------------------------------------------------------------------------
__global__ void k_prep_h2(const float* __restrict__ W1,
                          const float* __restrict__ last,
                          const float* __restrict__ W2,
                          const float* __restrict__ b1,
                          const float* __restrict__ b2) {
    if (blockIdx.x < 512) {
        int d = blockIdx.x;
        int u = threadIdx.x;
        g_wt[u * DD + d] = __float2half_rn(W1[d * UU + u]);
    } else {
        int b = blockIdx.x - 512;
        int u = threadIdx.x;
        __shared__ float sl[DD];
        sl[u] = last[b * DD + u];
        __syncthreads();
        float acc = 0.f;
#pragma unroll 8
        for (int d = 0; d < DD; ++d)
            acc += sl[d] * W2[d * UU + u];
        g_hb[b * UU + u] = acc + b1[u] + b2[u];
    }
}

// ---------------------------------------------------------------------------
// Kernel B: scores + FUSED partial context.  CTA = 64t x 512u x 512k.
// A fp16 resident; B streamed (4-stage cp.async ring, one barrier/chunk).
// Epilogue: exp(score) per row -> partial Z + partial weighted context from
// the smem-resident A tile.  No second read of `full` anywhere.
// ---------------------------------------------------------------------------
__global__ __launch_bounds__(256, 2) void k_score(
    const float* __restrict__ full, const float* __restrict__ V) {
    extern __shared__ __align__(16) char smem[];
    float* hb_s = (float*)(smem + OFF_HB);
    float* vs_s = (float*)(smem + OFF_VS);
    float* red  = (float*)(smem + OFF_RED);
    __half* sB  = (__half*)(smem + OFF_B);
    __half* sA  = (__half*)(smem + OFF_A);

    const int tid = threadIdx.x;
    const int wid = tid >> 5;
    const int lane = tid & 31;
    const int g = lane >> 2;
    const int t = lane & 3;
    const int mw = wid >> 2;
    const int nw = wid & 3;
    const int mbase = mw * 32;
    const int nbase = nw * 32;

    const int b  = blockIdx.y;
    const int tc = blockIdx.x;
    const int t0 = tc * 64;

    const int tile = lane >> 3;
    const int rr = lane & 7;
    const int a_lane_off = ((tile & 1) * 8 + rr) * PADA + ((tile >> 1) & 1) * 8;
    const int b_lane_off = (((tile >> 1) & 1) * 8 + rr) * PADB + (tile & 1) * 8;

    auto issueB = [&](int gc, int slot) {
        const int u0 = (gc >> 4) * 128;
        const int k0 = (gc & 15) * 32;
#pragma unroll
        for (int j = 0; j < 2; ++j) {
            int o   = tid + j * 256;
            int row = o >> 2;
            int q   = o & 3;
            const __half* src = g_wt + (size_t)(u0 + row) * DD + k0 + q * 8;
            __half* dst = sB + slot * B_STAGE_H + row * PADB + q * 8;
            cp16(dst, src);
        }
        cp_commit();
    };

    issueB(0, 0);
    issueB(1, 1);
    issueB(2, 2);

    {
        const float* Ab = full + ((size_t)(b * TT + t0)) * DD;
#pragma unroll
        for (int it = 0; it < 32; ++it) {
            int idx = tid + it * 256;
            int r = idx >> 7;
            int q = idx & 127;
            float4 v4 = *(const float4*)(Ab + (size_t)r * DD + q * 4);
            uint2 hv;
            hv.x = pack2h(__float2half_rn(v4.x), __float2half_rn(v4.y));
            hv.y = pack2h(__float2half_rn(v4.z), __float2half_rn(v4.w));
            *(uint2*)(sA + r * PADA + q * 4) = hv;
        }
    }

    float s[4];
#pragma unroll
    for (int i = 0; i < 4; ++i) s[i] = 0.f;
    float acc[32];

    for (int gc = 0; gc < 64; ++gc) {
        const int slot = gc & 3;
        if (gc <= 61) cp_wait2();
        else if (gc == 62) cp_wait1();
        else cp_wait0();
        __syncthreads();

        if ((gc & 15) == 0) {
            int uc = gc >> 4;
            if (tid < 128) {
                hb_s[tid] = g_hb[b * UU + uc * 128 + tid];
                vs_s[tid] = V[uc * 128 + tid];
            }
#pragma unroll
            for (int i = 0; i < 32; ++i) acc[i] = 0.f;
        }
        if (gc + 3 < 64) issueB(gc + 3, (gc + 3) & 3);

        const __half* Bh = sB + slot * B_STAGE_H;
        const int k0 = (gc & 15) * 32;
#pragma unroll
        for (int kk = 0; kk < 32; kk += 16) {
            unsigned bh[8];
#pragma unroll
            for (int p = 0; p < 2; ++p)
                ldm4(bh + 4 * p, Bh + (nbase + p * 16) * PADB + kk + b_lane_off);
#pragma unroll
            for (int mt = 0; mt < 2; ++mt) {
                unsigned ah[4];
                ldm4(ah, sA + (mbase + mt * 16) * PADA + k0 + kk + a_lane_off);
#pragma unroll
                for (int nt = 0; nt < 4; ++nt)
                    mma16816(acc + (mt * 4 + nt) * 4, ah, bh + 2 * nt);
            }
        }

        if ((gc & 15) == 15) {
#pragma unroll
            for (int mt = 0; mt < 2; ++mt) {
#pragma unroll
                for (int nt = 0; nt < 4; ++nt) {
                    const float* cc = acc + (mt * 4 + nt) * 4;
                    int n0 = nbase + nt * 8 + 2 * t;
                    s[mt * 2 + 0] += fast_tanh(cc[0] + hb_s[n0]) * vs_s[n0]
                                   + fast_tanh(cc[1] + hb_s[n0 + 1]) * vs_s[n0 + 1];
                    s[mt * 2 + 1] += fast_tanh(cc[2] + hb_s[n0]) * vs_s[n0]
                                   + fast_tanh(cc[3] + hb_s[n0 + 1]) * vs_s[n0 + 1];
                }
            }
        }
    }

    // ---- score reduce: t lanes (width 4), then 4 nw-warps via smem ----
#pragma unroll
    for (int i = 0; i < 4; ++i) {
        float v = s[i];
        v += __shfl_xor_sync(0xffffffffu, v, 1, 4);
        v += __shfl_xor_sync(0xffffffffu, v, 2, 4);
        if (t == 0) {
            int mt = i >> 1, half = i & 1;
            int row = mbase + mt * 16 + half * 8 + g;
            red[nw * 64 + row] = v;
        }
    }
    __syncthreads();

    // ---- exp(score) per row (bV cancels in softmax) ----
    float* ws = hb_s;              // reuse (hb/vs dead after last epilogue)
    if (tid < 64) {
        float sum = red[tid] + red[64 + tid] + red[128 + tid] + red[192 + tid];
        ws[tid] = expf(sum);
    }
    __syncthreads();

    // ---- partial Z ----
    if (tid == 0) {
        float z = 0.f;
#pragma unroll
        for (int i = 0; i < 64; ++i) z += ws[i];
        g_zpart[b * TCH + tc] = z;
    }

    // ---- partial weighted context from smem A tile (fp16) ----
    {
        float2 cacc = make_float2(0.f, 0.f);
#pragma unroll 8
        for (int r = 0; r < 64; ++r) {
            __half2 a = *(const __half2*)(sA + r * PADA + 2 * tid);
            float2 f = __half22float2(a);
            float w = ws[r];
            cacc.x += w * f.x;
            cacc.y += w * f.y;
        }
        ((float2*)(g_part + ((size_t)(b * TCH + tc)) * DD))[tid] = cacc;
    }
}

// ---------------------------------------------------------------------------
// Kernel C: combine partials + Z, divide.  grid (4, BB) x 128 thr.
// ---------------------------------------------------------------------------
__global__ void k_combine(float* __restrict__ out) {
    int b = blockIdx.y;
    int d = blockIdx.x * 128 + threadIdx.x;
    __shared__ float zs;
    if (threadIdx.x == 0) {
        float z = 0.f;
#pragma unroll
        for (int tc = 0; tc < TCH; ++tc) z += g_zpart[b * TCH + tc];
        zs = z;
    }
    __syncthreads();
    float acc = 0.f;
#pragma unroll
    for (int tc = 0; tc < TCH; ++tc)
        acc += g_part[((size_t)(b * TCH + tc)) * DD + d];
    out[b * DD + d] = acc / zs;
}

// ---------------------------------------------------------------------------
extern "C" void kernel_launch(void* const* d_in, const int* in_sizes, int n_in,
                              void* d_out, int out_size) {
    const float* full = (const float*)d_in[0];
    const float* last = (const float*)d_in[1];
    const float* W1   = (const float*)d_in[2];
    const float* b1   = (const float*)d_in[3];
    const float* W2   = (const float*)d_in[4];
    const float* b2   = (const float*)d_in[5];
    const float* V    = (const float*)d_in[6];
    float* out = (float*)d_out;

    cudaFuncSetAttribute(k_score, cudaFuncAttributeMaxDynamicSharedMemorySize,
                         SMEM_TOTAL);

    k_prep_h2<<<544, 512>>>(W1, last, W2, b1, b2);

    dim3 gScore(TCH, BB);
    k_score<<<gScore, 256, SMEM_TOTAL>>>(full, V);

    dim3 gComb(4, BB);
    k_combine<<<gComb, 128>>>(out);
}

// round 11
// speedup vs baseline: 2.7957x; 1.1733x over previous
#include <cuda_runtime.h>
#include <cuda_fp16.h>
#include <cstdint>
#include <math.h>

#define BB 32
#define TT 2048
#define DD 512
#define UU 512

#define TCH 32                 // t-chunks per batch (= grid.x of k_score)

// ---- scratch ----
__device__ float g_hpart[BB * 4 * UU];   // split-k h2 partials (+b1+b2 in ks=0)
__device__ float g_zpart[BB * TCH];
__device__ float g_part[BB * TCH * DD];
__device__ __half g_w16[DD * UU];        // W1 fp16, native [d][u] layout

// ---------------- helpers ----------------
static __device__ __forceinline__ unsigned pack2h(__half a, __half b) {
    return (unsigned)__half_as_ushort(a) |
           ((unsigned)__half_as_ushort(b) << 16);
}
static __device__ __forceinline__ float fast_tanh(float x) {
    float e = __expf(2.f * x);
    return 1.f - __fdividef(2.f, e + 1.f);
}
static __device__ __forceinline__ void mma16816(float* c, const unsigned* a, const unsigned* b) {
    asm volatile(
        "mma.sync.aligned.m16n8k16.row.col.f32.f16.f16.f32 "
        "{%0,%1,%2,%3}, {%4,%5,%6,%7}, {%8,%9}, {%0,%1,%2,%3};"
        : "+f"(c[0]), "+f"(c[1]), "+f"(c[2]), "+f"(c[3])
        : "r"(a[0]), "r"(a[1]), "r"(a[2]), "r"(a[3]), "r"(b[0]), "r"(b[1]));
}
static __device__ __forceinline__ void ldm4(unsigned* r, const void* p) {
    unsigned addr = (unsigned)__cvta_generic_to_shared(p);
    asm volatile(
        "ldmatrix.sync.aligned.m8n8.x4.shared.b16 {%0,%1,%2,%3}, [%4];"
        : "=r"(r[0]), "=r"(r[1]), "=r"(r[2]), "=r"(r[3])
        : "r"(addr));
}
static __device__ __forceinline__ void ldm4t(unsigned* r, const void* p) {
    unsigned addr = (unsigned)__cvta_generic_to_shared(p);
    asm volatile(
        "ldmatrix.sync.aligned.m8n8.x4.trans.shared.b16 {%0,%1,%2,%3}, [%4];"
        : "=r"(r[0]), "=r"(r[1]), "=r"(r[2]), "=r"(r[3])
        : "r"(addr));
}
static __device__ __forceinline__ void cp16(void* dst, const void* src) {
    unsigned d = (unsigned)__cvta_generic_to_shared(dst);
    asm volatile("cp.async.cg.shared.global [%0], [%1], 16;"
                 :: "r"(d), "l"(src) : "memory");
}
static __device__ __forceinline__ void cp_commit() {
    asm volatile("cp.async.commit_group;" ::: "memory");
}
static __device__ __forceinline__ void cp_wait2() {
    asm volatile("cp.async.wait_group 2;" ::: "memory");
}
static __device__ __forceinline__ void cp_wait1() {
    asm volatile("cp.async.wait_group 1;" ::: "memory");
}
static __device__ __forceinline__ void cp_wait0() {
    asm volatile("cp.async.wait_group 0;" ::: "memory");
}

// smem layout (halves unless noted)
#define PADA 520
#define PADB2 136                  // B row stride: 272 B, mod 128 = 16 -> conflict-free
#define NSTAGE 4
#define OFF_HB   0
#define OFF_VS   512
#define OFF_RED  1024
#define OFF_B    2048
#define B_STAGE_H (32 * PADB2)                         // 4352 halves = 8704 B
#define OFF_A    (OFF_B + NSTAGE * B_STAGE_H * 2)      // 2048 + 34816 = 36864
#define SMEM_TOTAL (OFF_A + 64 * PADA * 2)             // 103424 B

// ---------------------------------------------------------------------------
// Kernel A: fused (W1 fp32->fp16 elementwise) + (h2 split-k partials)
// grid 256 x 512 thr.  bid<128: convert 2048 elements.  bid>=128: h2 partial.
// ---------------------------------------------------------------------------
__global__ void k_pre(const float* __restrict__ W1,
                      const float* __restrict__ last,
                      const float* __restrict__ W2,
                      const float* __restrict__ b1,
                      const float* __restrict__ b2) {
    if (blockIdx.x < 128) {
        int gidx = blockIdx.x * 2048 + threadIdx.x * 4;
        float4 v = *(const float4*)(W1 + gidx);
        uint2 hv;
        hv.x = pack2h(__float2half_rn(v.x), __float2half_rn(v.y));
        hv.y = pack2h(__float2half_rn(v.z), __float2half_rn(v.w));
        *(uint2*)(g_w16 + gidx) = hv;
    } else {
        int bid = blockIdx.x - 128;
        int b  = bid >> 2;
        int ks = bid & 3;
        int u  = threadIdx.x;
        __shared__ float sl[128];
        if (u < 128) sl[u] = last[b * DD + ks * 128 + u];
        __syncthreads();
        float acc = 0.f;
        const float* w2p = W2 + (size_t)(ks * 128) * UU + u;
#pragma unroll 8
        for (int d = 0; d < 128; ++d)
            acc += sl[d] * w2p[(size_t)d * UU];
        if (ks == 0) acc += b1[u] + b2[u];
        g_hpart[(b * 4 + ks) * UU + u] = acc;
    }
}

// ---------------------------------------------------------------------------
// Kernel B: scores + fused partial context.  CTA = 64t x 512u x 512k.
// A fp16 resident; B = W1 fp16 native [k][u] rows streamed via 4-stage
// cp.async ring, consumed with ldmatrix.trans.  One barrier per k-chunk.
// ---------------------------------------------------------------------------
__global__ __launch_bounds__(256, 2) void k_score(
    const float* __restrict__ full, const float* __restrict__ V) {
    extern __shared__ __align__(16) char smem[];
    float* hb_s = (float*)(smem + OFF_HB);
    float* vs_s = (float*)(smem + OFF_VS);
    float* red  = (float*)(smem + OFF_RED);
    __half* sB  = (__half*)(smem + OFF_B);
    __half* sA  = (__half*)(smem + OFF_A);

    const int tid = threadIdx.x;
    const int wid = tid >> 5;
    const int lane = tid & 31;
    const int g = lane >> 2;
    const int t = lane & 3;
    const int mw = wid >> 2;
    const int nw = wid & 3;
    const int mbase = mw * 32;
    const int nbase = nw * 32;

    const int b  = blockIdx.y;
    const int tc = blockIdx.x;
    const int t0 = tc * 64;

    const int tile = lane >> 3;
    const int rr = lane & 7;
    const int a_lane_off = ((tile & 1) * 8 + rr) * PADA + ((tile >> 1) & 1) * 8;
    // trans-B: rows are k (tile&1 selects k-half), cols are u (tile>>1 selects u-half)
    const int bt_lane_off = ((tile & 1) * 8 + rr) * PADB2 + ((tile >> 1) & 1) * 8;

    auto issueB = [&](int gc, int slot) {
        const int u0 = (gc >> 4) * 128;
        const int k0 = (gc & 15) * 32;
#pragma unroll
        for (int j = 0; j < 2; ++j) {
            int o   = tid + j * 256;        // 0..511
            int row = o >> 4;               // k row 0..31
            int q   = o & 15;               // 16B chunk within 256B row
            const __half* src = g_w16 + (size_t)(k0 + row) * UU + u0 + q * 8;
            __half* dst = sB + slot * B_STAGE_H + row * PADB2 + q * 8;
            cp16(dst, src);
        }
        cp_commit();
    };

    issueB(0, 0);
    issueB(1, 1);
    issueB(2, 2);

    {
        const float* Ab = full + ((size_t)(b * TT + t0)) * DD;
#pragma unroll
        for (int it = 0; it < 32; ++it) {
            int idx = tid + it * 256;
            int r = idx >> 7;
            int q = idx & 127;
            float4 v4 = *(const float4*)(Ab + (size_t)r * DD + q * 4);
            uint2 hv;
            hv.x = pack2h(__float2half_rn(v4.x), __float2half_rn(v4.y));
            hv.y = pack2h(__float2half_rn(v4.z), __float2half_rn(v4.w));
            *(uint2*)(sA + r * PADA + q * 4) = hv;
        }
    }

    float s[4];
#pragma unroll
    for (int i = 0; i < 4; ++i) s[i] = 0.f;
    float acc[32];

    for (int gc = 0; gc < 64; ++gc) {
        const int slot = gc & 3;
        if (gc <= 61) cp_wait2();
        else if (gc == 62) cp_wait1();
        else cp_wait0();
        __syncthreads();

        if ((gc & 15) == 0) {
            int uc = gc >> 4;
            if (tid < 128) {
                int u = uc * 128 + tid;
                hb_s[tid] = g_hpart[(b * 4 + 0) * UU + u]
                          + g_hpart[(b * 4 + 1) * UU + u]
                          + g_hpart[(b * 4 + 2) * UU + u]
                          + g_hpart[(b * 4 + 3) * UU + u];
                vs_s[tid] = V[u];
            }
#pragma unroll
            for (int i = 0; i < 32; ++i) acc[i] = 0.f;
        }
        if (gc + 3 < 64) issueB(gc + 3, (gc + 3) & 3);

        const __half* Bh = sB + slot * B_STAGE_H;
        const int k0 = (gc & 15) * 32;
#pragma unroll
        for (int kk = 0; kk < 32; kk += 16) {
            unsigned bh[8];
#pragma unroll
            for (int p = 0; p < 2; ++p)
                ldm4t(bh + 4 * p, Bh + kk * PADB2 + nbase + p * 16 + bt_lane_off);
#pragma unroll
            for (int mt = 0; mt < 2; ++mt) {
                unsigned ah[4];
                ldm4(ah, sA + (mbase + mt * 16) * PADA + k0 + kk + a_lane_off);
#pragma unroll
                for (int nt = 0; nt < 4; ++nt)
                    mma16816(acc + (mt * 4 + nt) * 4, ah, bh + 2 * nt);
            }
        }

        if ((gc & 15) == 15) {
#pragma unroll
            for (int mt = 0; mt < 2; ++mt) {
#pragma unroll
                for (int nt = 0; nt < 4; ++nt) {
                    const float* cc = acc + (mt * 4 + nt) * 4;
                    int n0 = nbase + nt * 8 + 2 * t;
                    s[mt * 2 + 0] += fast_tanh(cc[0] + hb_s[n0]) * vs_s[n0]
                                   + fast_tanh(cc[1] + hb_s[n0 + 1]) * vs_s[n0 + 1];
                    s[mt * 2 + 1] += fast_tanh(cc[2] + hb_s[n0]) * vs_s[n0]
                                   + fast_tanh(cc[3] + hb_s[n0 + 1]) * vs_s[n0 + 1];
                }
            }
        }
    }

    // ---- score reduce: t lanes (width 4), then 4 nw-warps via smem ----
#pragma unroll
    for (int i = 0; i < 4; ++i) {
        float v = s[i];
        v += __shfl_xor_sync(0xffffffffu, v, 1, 4);
        v += __shfl_xor_sync(0xffffffffu, v, 2, 4);
        if (t == 0) {
            int mt = i >> 1, half = i & 1;
            int row = mbase + mt * 16 + half * 8 + g;
            red[nw * 64 + row] = v;
        }
    }
    __syncthreads();

    // ---- exp(score) per row (bV cancels in softmax) ----
    float* ws = hb_s;              // reuse
    if (tid < 64) {
        float sum = red[tid] + red[64 + tid] + red[128 + tid] + red[192 + tid];
        ws[tid] = expf(sum);
    }
    __syncthreads();

    if (tid == 0) {
        float z = 0.f;
#pragma unroll
        for (int i = 0; i < 64; ++i) z += ws[i];
        g_zpart[b * TCH + tc] = z;
    }

    // ---- partial weighted context from smem A tile (fp16) ----
    {
        float2 cacc = make_float2(0.f, 0.f);
#pragma unroll 8
        for (int r = 0; r < 64; ++r) {
            __half2 a = *(const __half2*)(sA + r * PADA + 2 * tid);
            float2 f = __half22float2(a);
            float w = ws[r];
            cacc.x += w * f.x;
            cacc.y += w * f.y;
        }
        ((float2*)(g_part + ((size_t)(b * TCH + tc)) * DD))[tid] = cacc;
    }
}

// ---------------------------------------------------------------------------
// Kernel C: combine partials + Z, divide.  grid (4, BB) x 128 thr.
// ---------------------------------------------------------------------------
__global__ void k_combine(float* __restrict__ out) {
    int b = blockIdx.y;
    int d = blockIdx.x * 128 + threadIdx.x;
    __shared__ float zs;
    if (threadIdx.x == 0) {
        float z = 0.f;
#pragma unroll
        for (int tc = 0; tc < TCH; ++tc) z += g_zpart[b * TCH + tc];
        zs = z;
    }
    __syncthreads();
    float acc = 0.f;
#pragma unroll
    for (int tc = 0; tc < TCH; ++tc)
        acc += g_part[((size_t)(b * TCH + tc)) * DD + d];
    out[b * DD + d] = acc / zs;
}

// ---------------------------------------------------------------------------
extern "C" void kernel_launch(void* const* d_in, const int* in_sizes, int n_in,
                              void* d_out, int out_size) {
    const float* full = (const float*)d_in[0];
    const float* last = (const float*)d_in[1];
    const float* W1   = (const float*)d_in[2];
    const float* b1   = (const float*)d_in[3];
    const float* W2   = (const float*)d_in[4];
    const float* b2   = (const float*)d_in[5];
    const float* V    = (const float*)d_in[6];
    float* out = (float*)d_out;

    cudaFuncSetAttribute(k_score, cudaFuncAttributeMaxDynamicSharedMemorySize,
                         SMEM_TOTAL);

    k_pre<<<256, 512>>>(W1, last, W2, b1, b2);

    dim3 gScore(TCH, BB);
    k_score<<<gScore, 256, SMEM_TOTAL>>>(full, V);

    dim3 gComb(4, BB);
    k_combine<<<gComb, 128>>>(out);
}